// round 3
// baseline (speedup 1.0000x reference)
#include <cuda_runtime.h>
#include <cuda_bf16.h>
#include <cstdint>

// Problem constants
#define B_   4
#define S_   2048
#define D_   1024
#define H_   16
#define DH   64
#define M_TOT (B_ * S_)        // 8192
#define N_QKV (3 * D_)         // 3072

typedef unsigned long long u64;

// ---------------------------------------------------------------------------
// Scratch (device globals; allocation inside kernel_launch is forbidden)
// ---------------------------------------------------------------------------
__device__ float g_q[(size_t)B_ * H_ * S_ * DH];    // [B,H,S,Dh]
__device__ float g_k[(size_t)B_ * H_ * S_ * DH];
__device__ float g_v[(size_t)B_ * H_ * S_ * DH];
__device__ float g_att[(size_t)B_ * S_ * D_];       // [B,S,D] pre-projection

// ---------------------------------------------------------------------------
// f32x2 helpers (Blackwell packed fp32 pipe; 2x FFMA throughput)
// ---------------------------------------------------------------------------
__device__ __forceinline__ u64 pack2(float x, float y) {
    u64 r;
    asm("mov.b64 %0, {%1, %2};" : "=l"(r)
        : "r"(__float_as_uint(x)), "r"(__float_as_uint(y)));
    return r;
}
__device__ __forceinline__ void unpack2(u64 v, float& x, float& y) {
    unsigned lo, hi;
    asm("mov.b64 {%0, %1}, %2;" : "=r"(lo), "=r"(hi) : "l"(v));
    x = __uint_as_float(lo);
    y = __uint_as_float(hi);
}
__device__ __forceinline__ void fma2(u64& d, u64 a, u64 b) {
    asm("fma.rn.f32x2 %0, %1, %2, %0;" : "+l"(d) : "l"(a), "l"(b));
}

// ---------------------------------------------------------------------------
// GEMM: C[M,N] = A[M,K] @ W[K,N] + bias   (128x128 tile, 8x8/thread, f32x2)
// MODE 0: A = x param, scatter epilogue into g_q/g_k/g_v
// MODE 1: A = g_att,   plain epilogue into C
// ---------------------------------------------------------------------------
__device__ __forceinline__ void qkv_scatter(int m, int n, float v) {
    int which = n >> 10;          // 0=q 1=k 2=v
    int rem   = n & 1023;
    int h     = rem >> 6;
    int dd    = rem & 63;
    int b     = m >> 11;
    int s     = m & 2047;
    size_t idx = (((size_t)(b * H_ + h)) * S_ + s) * DH + dd;
    float* dst = (which == 0) ? g_q : ((which == 1) ? g_k : g_v);
    dst[idx] = v;
}

template <int MODE>
__global__ __launch_bounds__(256, 2) void gemm128(
    const float* __restrict__ A,
    const float* __restrict__ W,
    const float* __restrict__ bias,
    float* __restrict__ C,
    int M, int N, int K)
{
    __shared__ __align__(16) float As[16][128];   // As[k][m]  (A transposed)
    __shared__ __align__(16) float Bs[16][128];   // Bs[k][n]

    const int tid = threadIdx.x;
    const int tx  = tid & 15;          // n-direction (x8)
    const int ty  = tid >> 4;          // m-direction (x8)
    const int bm  = blockIdx.y * 128;
    const int bn  = blockIdx.x * 128;

    const float* Ap = (MODE == 1) ? (const float*)g_att : A;

    u64 acc[4][8];                     // [m-pair][n]
#pragma unroll
    for (int i = 0; i < 4; i++)
#pragma unroll
        for (int j = 0; j < 8; j++) acc[i][j] = 0ull;

    const int a_row = tid >> 2;            // 0..63
    const int a_k   = (tid & 3) << 2;      // 0,4,8,12
    const int b_k   = tid >> 5;            // 0..7
    const int b_n   = (tid & 31) << 2;     // 0..124

    for (int k0 = 0; k0 < K; k0 += 16) {
        // load A tile (128 rows x 16 k), store transposed
#pragma unroll
        for (int p = 0; p < 2; p++) {
            int r = a_row + p * 64;
            float4 v = *reinterpret_cast<const float4*>(
                Ap + (size_t)(bm + r) * K + k0 + a_k);
            As[a_k + 0][r] = v.x;
            As[a_k + 1][r] = v.y;
            As[a_k + 2][r] = v.z;
            As[a_k + 3][r] = v.w;
        }
        // load B tile (16 k x 128 n)
#pragma unroll
        for (int p = 0; p < 2; p++) {
            int kr = b_k + p * 8;
            float4 v = *reinterpret_cast<const float4*>(
                W + (size_t)(k0 + kr) * N + bn + b_n);
            *reinterpret_cast<float4*>(&Bs[kr][b_n]) = v;
        }
        __syncthreads();

#pragma unroll
        for (int k = 0; k < 16; k++) {
            u64 a2[4];
#pragma unroll
            for (int i = 0; i < 4; i++)
                a2[i] = *reinterpret_cast<const u64*>(&As[k][ty * 8 + 2 * i]);
            float4 bv0 = *reinterpret_cast<const float4*>(&Bs[k][tx * 8]);
            float4 bv1 = *reinterpret_cast<const float4*>(&Bs[k][tx * 8 + 4]);
            u64 bd[8];
            bd[0] = pack2(bv0.x, bv0.x);
            bd[1] = pack2(bv0.y, bv0.y);
            bd[2] = pack2(bv0.z, bv0.z);
            bd[3] = pack2(bv0.w, bv0.w);
            bd[4] = pack2(bv1.x, bv1.x);
            bd[5] = pack2(bv1.y, bv1.y);
            bd[6] = pack2(bv1.z, bv1.z);
            bd[7] = pack2(bv1.w, bv1.w);
#pragma unroll
            for (int i = 0; i < 4; i++)
#pragma unroll
                for (int j = 0; j < 8; j++)
                    fma2(acc[i][j], a2[i], bd[j]);
        }
        __syncthreads();
    }

    // epilogue
#pragma unroll
    for (int i2 = 0; i2 < 4; i2++) {
        int m0 = bm + ty * 8 + 2 * i2;
#pragma unroll
        for (int j = 0; j < 8; j++) {
            int n = bn + tx * 8 + j;
            float bv = bias[n];
            float vlo, vhi;
            unpack2(acc[i2][j], vlo, vhi);
            vlo += bv;
            vhi += bv;
            if (MODE == 0) {
                qkv_scatter(m0,     n, vlo);
                qkv_scatter(m0 + 1, n, vhi);
            } else {
                C[(size_t)m0 * N + n]       = vlo;
                C[(size_t)(m0 + 1) * N + n] = vhi;
            }
        }
    }
}

// ---------------------------------------------------------------------------
// Flash attention, fp32. One CTA = one (b,h) x 64-query tile.
// Smem: Qs + Ks + Vs = 48KB exactly; P overlays Ks. Element XOR swizzle.
// ---------------------------------------------------------------------------
#define SWZ(r, c) ((((r)) << 6) + (((c) ^ (r))))

__global__ __launch_bounds__(256) void attn64()
{
    __shared__ __align__(16) float Qs[4096];
    __shared__ __align__(16) float Ks[4096];   // reused for P after S compute
    __shared__ __align__(16) float Vs[4096];

    const int tid = threadIdx.x;
    const int tx  = tid & 15;     // key / dhead cols (x4)
    const int ty  = tid >> 4;     // query rows (x4)
    const int bh  = blockIdx.y;   // b*16 + h
    const int b   = bh >> 4;
    const int h   = bh & 15;
    const int q0  = blockIdx.x * 64;

    const float* Qg = g_q + ((size_t)bh * S_ + q0) * DH;
    const float* Kg = g_k + (size_t)bh * S_ * DH;
    const float* Vg = g_v + (size_t)bh * S_ * DH;

    // load Q tile (scaled by Dh^-0.5)
#pragma unroll
    for (int p = 0; p < 4; p++) {
        int idx4 = tid + p * 256;
        int r = idx4 >> 4;
        int c = (idx4 & 15) << 2;
        float4 v = *reinterpret_cast<const float4*>(Qg + r * 64 + c);
        Qs[SWZ(r, c + 0)] = v.x * 0.125f;
        Qs[SWZ(r, c + 1)] = v.y * 0.125f;
        Qs[SWZ(r, c + 2)] = v.z * 0.125f;
        Qs[SWZ(r, c + 3)] = v.w * 0.125f;
    }

    float m_i[4], l_i[4], o[4][4];
#pragma unroll
    for (int i = 0; i < 4; i++) {
        m_i[i] = -1e30f;
        l_i[i] = 0.0f;
#pragma unroll
        for (int j = 0; j < 4; j++) o[i][j] = 0.0f;
    }

    for (int t = 0; t < S_ / 64; t++) {
        __syncthreads();   // prev PV done (and Q tile visible on t=0)

        // load K, V tiles (swizzled)
        const float* kt = Kg + (size_t)t * 64 * DH;
        const float* vt = Vg + (size_t)t * 64 * DH;
#pragma unroll
        for (int p = 0; p < 4; p++) {
            int idx4 = tid + p * 256;
            int r = idx4 >> 4;
            int c = (idx4 & 15) << 2;
            float4 kv = *reinterpret_cast<const float4*>(kt + r * 64 + c);
            Ks[SWZ(r, c + 0)] = kv.x;
            Ks[SWZ(r, c + 1)] = kv.y;
            Ks[SWZ(r, c + 2)] = kv.z;
            Ks[SWZ(r, c + 3)] = kv.w;
            float4 vv = *reinterpret_cast<const float4*>(vt + r * 64 + c);
            Vs[SWZ(r, c + 0)] = vv.x;
            Vs[SWZ(r, c + 1)] = vv.y;
            Vs[SWZ(r, c + 2)] = vv.z;
            Vs[SWZ(r, c + 3)] = vv.w;
        }
        __syncthreads();

        // S = Q K^T  (4x4 per thread)
        float s[4][4];
#pragma unroll
        for (int i = 0; i < 4; i++)
#pragma unroll
            for (int j = 0; j < 4; j++) s[i][j] = 0.0f;

#pragma unroll 4
        for (int d = 0; d < 64; d++) {
            float qv[4], kv[4];
#pragma unroll
            for (int i = 0; i < 4; i++) qv[i] = Qs[SWZ(4 * ty + i, d)];
#pragma unroll
            for (int j = 0; j < 4; j++) kv[j] = Ks[SWZ(4 * tx + j, d)];
#pragma unroll
            for (int i = 0; i < 4; i++)
#pragma unroll
                for (int j = 0; j < 4; j++) s[i][j] += qv[i] * kv[j];
        }

        // online softmax (row groups of 16 lanes: shfl_xor 1,2,4,8)
        float p_[4][4];
#pragma unroll
        for (int i = 0; i < 4; i++) {
            float rm = fmaxf(fmaxf(s[i][0], s[i][1]), fmaxf(s[i][2], s[i][3]));
            rm = fmaxf(rm, __shfl_xor_sync(0xffffffffu, rm, 1));
            rm = fmaxf(rm, __shfl_xor_sync(0xffffffffu, rm, 2));
            rm = fmaxf(rm, __shfl_xor_sync(0xffffffffu, rm, 4));
            rm = fmaxf(rm, __shfl_xor_sync(0xffffffffu, rm, 8));
            float mn   = fmaxf(m_i[i], rm);
            float corr = __expf(m_i[i] - mn);
            float rs = 0.0f;
#pragma unroll
            for (int j = 0; j < 4; j++) {
                p_[i][j] = __expf(s[i][j] - mn);
                rs += p_[i][j];
            }
            rs += __shfl_xor_sync(0xffffffffu, rs, 1);
            rs += __shfl_xor_sync(0xffffffffu, rs, 2);
            rs += __shfl_xor_sync(0xffffffffu, rs, 4);
            rs += __shfl_xor_sync(0xffffffffu, rs, 8);
            l_i[i] = l_i[i] * corr + rs;
            m_i[i] = mn;
#pragma unroll
            for (int j = 0; j < 4; j++) o[i][j] *= corr;
        }

        __syncthreads();   // everyone done reading Ks
        // write P over Ks
#pragma unroll
        for (int i = 0; i < 4; i++)
#pragma unroll
            for (int j = 0; j < 4; j++)
                Ks[SWZ(4 * ty + i, 4 * tx + j)] = p_[i][j];
        __syncthreads();

        // O += P V
#pragma unroll 4
        for (int kk = 0; kk < 64; kk++) {
            float pv[4], vv[4];
#pragma unroll
            for (int i = 0; i < 4; i++) pv[i] = Ks[SWZ(4 * ty + i, kk)];
#pragma unroll
            for (int j = 0; j < 4; j++) vv[j] = Vs[SWZ(kk, 4 * tx + j)];
#pragma unroll
            for (int i = 0; i < 4; i++)
#pragma unroll
                for (int j = 0; j < 4; j++) o[i][j] += pv[i] * vv[j];
        }
    }

    // normalize + write to g_att[b][s][h*64+d]
#pragma unroll
    for (int i = 0; i < 4; i++) {
        float inv = 1.0f / l_i[i];
        int srow = q0 + 4 * ty + i;
#pragma unroll
        for (int j = 0; j < 4; j++) {
            g_att[((size_t)(b * S_ + srow)) * D_ + h * 64 + 4 * tx + j] =
                o[i][j] * inv;
        }
    }
}

// ---------------------------------------------------------------------------
// kernel_launch
// ---------------------------------------------------------------------------
extern "C" void kernel_launch(void* const* d_in, const int* in_sizes, int n_in,
                              void* d_out, int out_size)
{
    const float* x     = (const float*)d_in[0];
    const float* Wqkv  = (const float*)d_in[1];
    const float* bqkv  = (const float*)d_in[2];
    const float* Wout  = (const float*)d_in[3];
    const float* bout  = (const float*)d_in[4];
    float* out = (float*)d_out;

    // 1) QKV projection + scatter to [B,H,S,Dh]
    dim3 g1(N_QKV / 128, M_TOT / 128);   // (24, 64)
    gemm128<0><<<g1, 256>>>(x, Wqkv, bqkv, nullptr, M_TOT, N_QKV, D_);

    // 2) flash attention -> g_att [B,S,D]
    dim3 ga(S_ / 64, B_ * H_);           // (32, 64)
    attn64<<<ga, 256>>>();

    // 3) output projection
    dim3 g2(D_ / 128, M_TOT / 128);      // (8, 64)
    gemm128<1><<<g2, 256>>>(nullptr, Wout, bout, out, M_TOT, D_, D_);
}

// round 4
// speedup vs baseline: 1.7081x; 1.7081x over previous
#include <cuda_runtime.h>
#include <cuda_bf16.h>
#include <cstdint>

// Problem constants
#define B_   4
#define S_   2048
#define D_   1024
#define H_   16
#define DH   64
#define M_TOT (B_ * S_)        // 8192
#define N_QKV (3 * D_)         // 3072

typedef unsigned long long u64;

// ---------------------------------------------------------------------------
// Scratch (device globals; allocation inside kernel_launch is forbidden)
// ---------------------------------------------------------------------------
__device__ float g_q[(size_t)B_ * H_ * S_ * DH];    // [B,H,S,Dh]
__device__ float g_k[(size_t)B_ * H_ * S_ * DH];
__device__ float g_v[(size_t)B_ * H_ * S_ * DH];
__device__ float g_att[(size_t)B_ * S_ * D_];       // [B,S,D] pre-projection

// ---------------------------------------------------------------------------
// f32x2 helpers (Blackwell packed fp32 pipe; 2x FFMA throughput)
// ---------------------------------------------------------------------------
__device__ __forceinline__ u64 pack2(float x, float y) {
    u64 r;
    asm("mov.b64 %0, {%1, %2};" : "=l"(r)
        : "r"(__float_as_uint(x)), "r"(__float_as_uint(y)));
    return r;
}
__device__ __forceinline__ void unpack2(u64 v, float& x, float& y) {
    unsigned lo, hi;
    asm("mov.b64 {%0, %1}, %2;" : "=r"(lo), "=r"(hi) : "l"(v));
    x = __uint_as_float(lo);
    y = __uint_as_float(hi);
}
__device__ __forceinline__ void fma2(u64& d, u64 a, u64 b) {
    asm("fma.rn.f32x2 %0, %1, %2, %0;" : "+l"(d) : "l"(a), "l"(b));
}
__device__ __forceinline__ void mul2(u64& d, u64 c) {
    asm("mul.rn.f32x2 %0, %0, %1;" : "+l"(d) : "l"(c));
}

// ---------------------------------------------------------------------------
// GEMM: C[M,N] = A[M,K] @ W[K,N] + bias   (128x128 tile, 8x8/thread, f32x2)
// MODE 0: A = x param, scatter epilogue into g_q/g_k/g_v
// MODE 1: A = g_att,   plain epilogue into C
// ---------------------------------------------------------------------------
__device__ __forceinline__ void qkv_scatter(int m, int n, float v) {
    int which = n >> 10;          // 0=q 1=k 2=v
    int rem   = n & 1023;
    int h     = rem >> 6;
    int dd    = rem & 63;
    int b     = m >> 11;
    int s     = m & 2047;
    size_t idx = (((size_t)(b * H_ + h)) * S_ + s) * DH + dd;
    float* dst = (which == 0) ? g_q : ((which == 1) ? g_k : g_v);
    dst[idx] = v;
}

template <int MODE>
__global__ __launch_bounds__(256, 2) void gemm128(
    const float* __restrict__ A,
    const float* __restrict__ W,
    const float* __restrict__ bias,
    float* __restrict__ C,
    int M, int N, int K)
{
    __shared__ __align__(16) float As[16][128];   // As[k][m]  (A transposed)
    __shared__ __align__(16) float Bs[16][128];   // Bs[k][n]

    const int tid = threadIdx.x;
    const int tx  = tid & 15;          // n-direction (x8)
    const int ty  = tid >> 4;          // m-direction (x8)
    const int bm  = blockIdx.y * 128;
    const int bn  = blockIdx.x * 128;

    const float* Ap = (MODE == 1) ? (const float*)g_att : A;

    u64 acc[4][8];                     // [m-pair][n]
#pragma unroll
    for (int i = 0; i < 4; i++)
#pragma unroll
        for (int j = 0; j < 8; j++) acc[i][j] = 0ull;

    const int a_row = tid >> 2;            // 0..63
    const int a_k   = (tid & 3) << 2;      // 0,4,8,12
    const int b_k   = tid >> 5;            // 0..7
    const int b_n   = (tid & 31) << 2;     // 0..124

    for (int k0 = 0; k0 < K; k0 += 16) {
        // load A tile (128 rows x 16 k), store transposed
#pragma unroll
        for (int p = 0; p < 2; p++) {
            int r = a_row + p * 64;
            float4 v = *reinterpret_cast<const float4*>(
                Ap + (size_t)(bm + r) * K + k0 + a_k);
            As[a_k + 0][r] = v.x;
            As[a_k + 1][r] = v.y;
            As[a_k + 2][r] = v.z;
            As[a_k + 3][r] = v.w;
        }
        // load B tile (16 k x 128 n)
#pragma unroll
        for (int p = 0; p < 2; p++) {
            int kr = b_k + p * 8;
            float4 v = *reinterpret_cast<const float4*>(
                W + (size_t)(k0 + kr) * N + bn + b_n);
            *reinterpret_cast<float4*>(&Bs[kr][b_n]) = v;
        }
        __syncthreads();

#pragma unroll
        for (int k = 0; k < 16; k++) {
            u64 a2[4];
#pragma unroll
            for (int i = 0; i < 4; i++)
                a2[i] = *reinterpret_cast<const u64*>(&As[k][ty * 8 + 2 * i]);
            float4 bv0 = *reinterpret_cast<const float4*>(&Bs[k][tx * 8]);
            float4 bv1 = *reinterpret_cast<const float4*>(&Bs[k][tx * 8 + 4]);
            u64 bd[8];
            bd[0] = pack2(bv0.x, bv0.x);
            bd[1] = pack2(bv0.y, bv0.y);
            bd[2] = pack2(bv0.z, bv0.z);
            bd[3] = pack2(bv0.w, bv0.w);
            bd[4] = pack2(bv1.x, bv1.x);
            bd[5] = pack2(bv1.y, bv1.y);
            bd[6] = pack2(bv1.z, bv1.z);
            bd[7] = pack2(bv1.w, bv1.w);
#pragma unroll
            for (int i = 0; i < 4; i++)
#pragma unroll
                for (int j = 0; j < 8; j++)
                    fma2(acc[i][j], a2[i], bd[j]);
        }
        __syncthreads();
    }

    // epilogue
#pragma unroll
    for (int i2 = 0; i2 < 4; i2++) {
        int m0 = bm + ty * 8 + 2 * i2;
#pragma unroll
        for (int j = 0; j < 8; j++) {
            int n = bn + tx * 8 + j;
            float bv = bias[n];
            float vlo, vhi;
            unpack2(acc[i2][j], vlo, vhi);
            vlo += bv;
            vhi += bv;
            if (MODE == 0) {
                qkv_scatter(m0,     n, vlo);
                qkv_scatter(m0 + 1, n, vhi);
            } else {
                C[(size_t)m0 * N + n]       = vlo;
                C[(size_t)(m0 + 1) * N + n] = vhi;
            }
        }
    }
}

// ---------------------------------------------------------------------------
// Flash attention v2: 128 queries x 128-key tiles, f32x2 8x8 micro-tiles.
// Dynamic smem 128KB:
//   Qs [64][128]  (Q^T, pair-preserving rotate)          floats [0, 8192)
//   Ks [128][64]  (rotate by 2*(row>>3))                 floats [8192, 16384)
//   Ps [128][128] (P^T, rotate by key>>3; OVERLAYS Ks)   floats [8192, 24576)
//   Vs [128][64]  (identity)                             floats [24576, 32768)
// ---------------------------------------------------------------------------
#define ATTN_SMEM_BYTES (32768 * 4)

__global__ __launch_bounds__(256, 1) void attn128()
{
    extern __shared__ float sm[];
    float* Qs = sm;
    float* Ks = sm + 8192;
    float* Ps = sm + 8192;     // overlays Ks + 8192 more
    float* Vs = sm + 24576;

    const int tid = threadIdx.x;
    const int tx  = tid & 15;     // key groups (x8) in S; dh columns in PV
    const int ty  = tid >> 4;     // query groups (x8)
    const int bh  = blockIdx.y;
    const int b   = bh >> 4;
    const int h   = bh & 15;
    const int q0  = blockIdx.x * 128;

    const float* Qg = g_q + ((size_t)bh * S_ + q0) * DH;
    const float* Kg = g_k + (size_t)bh * S_ * DH;
    const float* Vg = g_v + (size_t)bh * S_ * DH;

    // ---- fill Q^T (scaled by Dh^-0.5) ----
#pragma unroll
    for (int p = 0; p < 8; p++) {
        int idx = tid + p * 256;
        int r   = idx >> 4;          // q row 0..127
        int c0  = (idx & 15) << 2;   // d 0,4,..,60
        float4 v = *reinterpret_cast<const float4*>(Qg + r * DH + c0);
        float vals[4] = {v.x, v.y, v.z, v.w};
#pragma unroll
        for (int i = 0; i < 4; i++) {
            int d = c0 + i;
            Qs[d * 128 + (((r >> 1) + d) & 63) * 2 + (r & 1)] = vals[i] * 0.125f;
        }
    }

    float m_[8], l_[8];
    u64 o[4][4];
#pragma unroll
    for (int i = 0; i < 8; i++) { m_[i] = -1e30f; l_[i] = 0.0f; }
#pragma unroll
    for (int i = 0; i < 4; i++)
#pragma unroll
        for (int j = 0; j < 4; j++) o[i][j] = 0ull;

    for (int t = 0; t < S_ / 128; t++) {
        __syncthreads();   // prev PV done reading Ps/Vs (Q visible on t=0)

        // ---- fill K (rotated) and V (identity) ----
        const float* kt = Kg + (size_t)t * 128 * DH;
        const float* vt = Vg + (size_t)t * 128 * DH;
#pragma unroll
        for (int p = 0; p < 8; p++) {
            int idx = tid + p * 256;
            int r   = idx >> 4;
            int c0  = (idx & 15) << 2;
            float4 kv = *reinterpret_cast<const float4*>(kt + r * DH + c0);
            float kvals[4] = {kv.x, kv.y, kv.z, kv.w};
            int rot = 2 * (r >> 3);
#pragma unroll
            for (int i = 0; i < 4; i++)
                Ks[r * 64 + ((c0 + i + rot) & 63)] = kvals[i];
            float4 vv = *reinterpret_cast<const float4*>(vt + r * DH + c0);
            *reinterpret_cast<float4*>(Vs + r * 64 + c0) = vv;
        }
        __syncthreads();

        // ---- S = Q K^T : 8 q-rows (4 pairs) x 8 keys per thread ----
        u64 s[4][8];
#pragma unroll
        for (int i = 0; i < 4; i++)
#pragma unroll
            for (int j = 0; j < 8; j++) s[i][j] = 0ull;

        const int krow = 8 * tx;
        const int krot = 2 * tx;
#pragma unroll 4
        for (int d = 0; d < 64; d++) {
            u64 a[4];
#pragma unroll
            for (int i = 0; i < 4; i++)
                a[i] = *reinterpret_cast<const u64*>(
                    &Qs[d * 128 + ((4 * ty + i + d) & 63) * 2]);
            u64 bb[8];
#pragma unroll
            for (int j = 0; j < 8; j++) {
                float kv = Ks[(krow + j) * 64 + ((d + krot) & 63)];
                bb[j] = pack2(kv, kv);
            }
#pragma unroll
            for (int i = 0; i < 4; i++)
#pragma unroll
                for (int j = 0; j < 8; j++)
                    fma2(s[i][j], a[i], bb[j]);
        }

        // ---- online softmax (rows of 128 keys: 8 local + shfl over 16 lanes)
        float plo[4][8], phi[4][8];
#pragma unroll
        for (int i = 0; i < 4; i++) {
            float slo[8], shi[8];
#pragma unroll
            for (int j = 0; j < 8; j++) unpack2(s[i][j], slo[j], shi[j]);

            float rm0 = slo[0], rm1 = shi[0];
#pragma unroll
            for (int j = 1; j < 8; j++) {
                rm0 = fmaxf(rm0, slo[j]);
                rm1 = fmaxf(rm1, shi[j]);
            }
#pragma unroll
            for (int w = 1; w < 16; w <<= 1) {
                rm0 = fmaxf(rm0, __shfl_xor_sync(0xffffffffu, rm0, w));
                rm1 = fmaxf(rm1, __shfl_xor_sync(0xffffffffu, rm1, w));
            }
            float mn0 = fmaxf(m_[2 * i],     rm0);
            float mn1 = fmaxf(m_[2 * i + 1], rm1);
            float c0 = __expf(m_[2 * i]     - mn0);
            float c1 = __expf(m_[2 * i + 1] - mn1);
            float sum0 = 0.0f, sum1 = 0.0f;
#pragma unroll
            for (int j = 0; j < 8; j++) {
                plo[i][j] = __expf(slo[j] - mn0);
                phi[i][j] = __expf(shi[j] - mn1);
                sum0 += plo[i][j];
                sum1 += phi[i][j];
            }
#pragma unroll
            for (int w = 1; w < 16; w <<= 1) {
                sum0 += __shfl_xor_sync(0xffffffffu, sum0, w);
                sum1 += __shfl_xor_sync(0xffffffffu, sum1, w);
            }
            l_[2 * i]     = l_[2 * i]     * c0 + sum0;
            l_[2 * i + 1] = l_[2 * i + 1] * c1 + sum1;
            m_[2 * i]     = mn0;
            m_[2 * i + 1] = mn1;
            u64 cc = pack2(c0, c1);
#pragma unroll
            for (int j = 0; j < 4; j++) mul2(o[i][j], cc);
        }

        __syncthreads();   // all Ks reads done -> safe to overwrite with Ps

        // ---- store P^T (pairs along q; rotate col by key>>3 = tx) ----
#pragma unroll
        for (int i = 0; i < 4; i++) {
            int col = ((4 * ty + i + tx) & 63) * 2;
#pragma unroll
            for (int j = 0; j < 8; j++) {
                *reinterpret_cast<u64*>(&Ps[(krow + j) * 128 + col]) =
                    pack2(plo[i][j], phi[i][j]);
            }
        }
        __syncthreads();

        // ---- O += P V : 8 q-rows (4 pairs) x 4 dh cols (tx, tx+16, +32, +48)
#pragma unroll 4
        for (int kk = 0; kk < 128; kk++) {
            int kg = kk >> 3;
            u64 pr[4];
#pragma unroll
            for (int i = 0; i < 4; i++)
                pr[i] = *reinterpret_cast<const u64*>(
                    &Ps[kk * 128 + ((4 * ty + i + kg) & 63) * 2]);
            u64 vv[4];
#pragma unroll
            for (int j = 0; j < 4; j++) {
                float f = Vs[kk * 64 + tx + 16 * j];
                vv[j] = pack2(f, f);
            }
#pragma unroll
            for (int i = 0; i < 4; i++)
#pragma unroll
                for (int j = 0; j < 4; j++)
                    fma2(o[i][j], pr[i], vv[j]);
        }
    }

    // ---- normalize + write g_att[b][s][h*64 + c] ----
#pragma unroll
    for (int i = 0; i < 4; i++) {
        float inv0 = 1.0f / l_[2 * i];
        float inv1 = 1.0f / l_[2 * i + 1];
        int r0 = q0 + 8 * ty + 2 * i;
#pragma unroll
        for (int j = 0; j < 4; j++) {
            float lo, hi;
            unpack2(o[i][j], lo, hi);
            int col = h * 64 + tx + 16 * j;
            g_att[((size_t)(b * S_ + r0))     * D_ + col] = lo * inv0;
            g_att[((size_t)(b * S_ + r0 + 1)) * D_ + col] = hi * inv1;
        }
    }
}

// ---------------------------------------------------------------------------
// kernel_launch
// ---------------------------------------------------------------------------
extern "C" void kernel_launch(void* const* d_in, const int* in_sizes, int n_in,
                              void* d_out, int out_size)
{
    const float* x     = (const float*)d_in[0];
    const float* Wqkv  = (const float*)d_in[1];
    const float* bqkv  = (const float*)d_in[2];
    const float* Wout  = (const float*)d_in[3];
    const float* bout  = (const float*)d_in[4];
    float* out = (float*)d_out;

    cudaFuncSetAttribute(attn128,
                         cudaFuncAttributeMaxDynamicSharedMemorySize,
                         ATTN_SMEM_BYTES);

    // 1) QKV projection + scatter to [B,H,S,Dh]
    dim3 g1(N_QKV / 128, M_TOT / 128);   // (24, 64)
    gemm128<0><<<g1, 256>>>(x, Wqkv, bqkv, nullptr, M_TOT, N_QKV, D_);

    // 2) flash attention -> g_att [B,S,D]
    dim3 ga(S_ / 128, B_ * H_);          // (16, 64)
    attn128<<<ga, 256, ATTN_SMEM_BYTES>>>();

    // 3) output projection
    dim3 g2(D_ / 128, M_TOT / 128);      // (8, 64)
    gemm128<1><<<g2, 256>>>(nullptr, Wout, bout, out, M_TOT, D_, D_);
}